// round 12
// baseline (speedup 1.0000x reference)
#include <cuda_runtime.h>
#include <cstdint>

#define Bn    16
#define Sn    1024
#define Dn    512
#define KCn   12
#define Kn    10
#define NSC   8           // s-chunks per batch
#define CSL   128         // s per chunk (contiguous 256 KB per CTA)
#define NT    256

typedef unsigned long long ull;
#define ONE2 0x3f8000003f800000ull

__device__ ull   g_part[Bn * NSC][Kn][Dn / 2];   // 2.6 MB chunk partials
__device__ float g_asum[Bn * NSC][Kn];
__device__ int   g_cnt[Bn];

__device__ __forceinline__ void fma2(ull& acc, ull a, ull f) {
    asm("fma.rn.f32x2 %0, %1, %2, %0;" : "+l"(acc) : "l"(a), "l"(f));
}
// 256-bit streaming-persistent load (sm_103a requires v4.b64 for evict_last)
__device__ __forceinline__ void ldg256_el(const ull* p, ull& f0, ull& f1, ull& f2, ull& f3) {
    asm("ld.global.nc.L2::evict_last.v4.u64 {%0,%1,%2,%3}, [%4];"
        : "=l"(f0), "=l"(f1), "=l"(f2), "=l"(f3) : "l"(p));
}

__global__ __launch_bounds__(NT, 1)
void vlad_k1f(const float* __restrict__ feat, const float* __restrict__ score,
              const float* __restrict__ cluster, float* __restrict__ out)
{
    __shared__ __align__(16) ull Ash[CSL][Kn];   // duplicated {a,a} pairs, 10 KB
    __shared__ __align__(16) ull buf[64][40];    // 20 KB sub-group fold buffer
    __shared__ float wsum[4][Kn];
    __shared__ float asumT[Kn];
    __shared__ float invS[Kn];
    __shared__ float sqw[Kn][8];
    __shared__ int   isLast;

    const int tid = threadIdx.x;
    const int b  = blockIdx.x >> 3;
    const int sc = blockIdx.x & 7;
    const int chunk = b * NSC + sc;
    const int sub = tid >> 6;        // s-interleave subgroup 0..3
    const int l64 = tid & 63;        // 32B block within row (4 d-pairs)

    // ---- softmax: threads 0..127, one s-row each ----
    if (tid < CSL) {
        const float* sp = score + ((size_t)(b * Sn) + sc * CSL + tid) * KCn;
        float4 v0 = *(const float4*)sp;
        float4 v1 = *(const float4*)(sp + 4);
        float4 v2 = *(const float4*)(sp + 8);
        float v[KCn] = {v0.x, v0.y, v0.z, v0.w, v1.x, v1.y, v1.z, v1.w,
                        v2.x, v2.y, v2.z, v2.w};
        float sum = 0.f;
        #pragma unroll
        for (int k = 0; k < KCn; k++) { v[k] = __expf(v[k]); sum += v[k]; }
        float inv = 1.f / sum;
        #pragma unroll
        for (int k = 0; k < Kn; k++) {
            float a = v[k] * inv;
            unsigned int u = __float_as_uint(a);
            Ash[tid][k] = ((ull)u << 32) | (ull)u;
            float s = a;
            #pragma unroll
            for (int o = 16; o > 0; o >>= 1) s += __shfl_xor_sync(0xffffffffu, s, o);
            if ((tid & 31) == 0) wsum[tid >> 5][k] = s;
        }
    }
    __syncthreads();
    if (tid < Kn)
        g_asum[chunk][tid] = wsum[0][tid] + wsum[1][tid] + wsum[2][tid] + wsum[3][tid];

    // ---- main loop: thread owns 4 d-pairs (32 B); subgroup sub takes rows s+sub ----
    ull acc[Kn][4];
    #pragma unroll
    for (int k = 0; k < Kn; k++) { acc[k][0] = acc[k][1] = acc[k][2] = acc[k][3] = 0ull; }

    const ull* fp = (const ull*)feat
                  + ((size_t)(b * Sn) + sc * CSL + sub) * (Dn / 2) + l64 * 4;

    #pragma unroll 2
    for (int s = 0; s < CSL; s += 4) {
        ull f0, f1, f2, f3;
        ldg256_el(fp + (size_t)s * (Dn / 2), f0, f1, f2, f3);
        const ulonglong2* ar = (const ulonglong2*)Ash[s + sub];   // warp-uniform
        ulonglong2 a01 = ar[0], a23 = ar[1], a45 = ar[2], a67 = ar[3], a89 = ar[4];
        #define ROW(kk, av) \
            fma2(acc[kk][0], av, f0); fma2(acc[kk][1], av, f1); \
            fma2(acc[kk][2], av, f2); fma2(acc[kk][3], av, f3);
        ROW(0, a01.x) ROW(1, a01.y) ROW(2, a23.x) ROW(3, a23.y) ROW(4, a45.x)
        ROW(5, a45.y) ROW(6, a67.x) ROW(7, a67.y) ROW(8, a89.x) ROW(9, a89.y)
        #undef ROW
    }

    // ---- fold the 4 s-subgroups (3-step smem tree, R4 pattern) ----
    ull* accp = &acc[0][0];
    if (sub == 1) {
        #pragma unroll
        for (int j = 0; j < 40; j++) buf[l64][j] = accp[j];
    }
    __syncthreads();
    if (sub == 0) {
        #pragma unroll
        for (int j = 0; j < 40; j++) fma2(accp[j], buf[l64][j], ONE2);
    }
    __syncthreads();
    if (sub == 3) {
        #pragma unroll
        for (int j = 0; j < 40; j++) buf[l64][j] = accp[j];
    }
    __syncthreads();
    if (sub == 2) {
        #pragma unroll
        for (int j = 0; j < 40; j++) fma2(accp[j], buf[l64][j], ONE2);
    }
    __syncthreads();
    if (sub == 2) {
        #pragma unroll
        for (int j = 0; j < 40; j++) buf[l64][j] = accp[j];
    }
    __syncthreads();
    if (sub == 0) {
        #pragma unroll
        for (int j = 0; j < 40; j++) fma2(accp[j], buf[l64][j], ONE2);
        // write chunk partial: pairs l64*4 .. l64*4+3 for each k
        #pragma unroll
        for (int k = 0; k < Kn; k++) {
            *(ulonglong2*)&g_part[chunk][k][l64 * 4]     = make_ulonglong2(acc[k][0], acc[k][1]);
            *(ulonglong2*)&g_part[chunk][k][l64 * 4 + 2] = make_ulonglong2(acc[k][2], acc[k][3]);
        }
    }

    // ---- last CTA of this batch merges the 8 chunk partials ----
    __threadfence();
    __syncthreads();
    if (tid == 0) isLast = (atomicAdd(&g_cnt[b], 1) == NSC - 1);
    __syncthreads();
    if (!isLast) return;
    __threadfence();

    if (tid < Kn) {
        float s = 0.f;
        #pragma unroll
        for (int c = 0; c < NSC; c++) s += g_asum[b * NSC + c][tid];
        asumT[tid] = s;
    }
    __syncthreads();

    float2 r[Kn];
    #pragma unroll
    for (int k = 0; k < Kn; k++) {
        ull a = g_part[b * NSC][k][tid];
        #pragma unroll
        for (int c = 1; c < NSC; c++) fma2(a, g_part[b * NSC + c][k][tid], ONE2);
        const float as = asumT[k];
        float2 cl = *(const float2*)(cluster + k * Dn + tid * 2);
        r[k].x = __uint_as_float((unsigned int)a)         - as * cl.x;
        r[k].y = __uint_as_float((unsigned int)(a >> 32)) - as * cl.y;
        float s = r[k].x * r[k].x + r[k].y * r[k].y;
        #pragma unroll
        for (int o = 16; o > 0; o >>= 1) s += __shfl_xor_sync(0xffffffffu, s, o);
        if ((tid & 31) == 0) sqw[k][tid >> 5] = s;
    }
    __syncthreads();
    if (tid < Kn) {
        float s = 0.f;
        #pragma unroll
        for (int w = 0; w < 8; w++) s += sqw[tid][w];
        invS[tid] = rsqrtf(fmaxf(s, 1e-12f));
    }
    __syncthreads();

    ull* ob = (ull*)out + (size_t)b * (Kn * Dn / 2);
    #pragma unroll
    for (int k = 0; k < Kn; k++) {
        const float iv = invS[k];
        unsigned int ux = __float_as_uint(r[k].x * iv);
        unsigned int uy = __float_as_uint(r[k].y * iv);
        ob[k * (Dn / 2) + tid] = ((ull)uy << 32) | (ull)ux;
    }
    if (tid == 0) g_cnt[b] = 0;   // reset for next graph replay
}

extern "C" void kernel_launch(void* const* d_in, const int* in_sizes, int n_in,
                              void* d_out, int out_size) {
    const float* feat    = (const float*)d_in[0];  // (16,16,64,512) f32
    const float* score   = (const float*)d_in[1];  // (16,16,64,12)  f32
    const float* cluster = (const float*)d_in[2];  // (12,512)       f32
    float* out = (float*)d_out;                    // (16,5120)      f32

    vlad_k1f<<<Bn * NSC, NT>>>(feat, score, cluster, out);
}

// round 13
// speedup vs baseline: 1.1385x; 1.1385x over previous
#include <cuda_runtime.h>
#include <cstdint>

#define Bn    16
#define Sn    1024
#define Dn    512
#define KCn   12
#define Kn    10
#define NSC   8           // s-chunks per batch -> 128 CTAs, single wave
#define CSL   128         // s-rows per chunk (contiguous 256 KB)
#define NT    256
#define SR    16          // rows per stage (32 KB)
#define NSTG  (CSL / SR)  // 8 stages
#define NSLOT 4
#define PFD   3
#define SLOTB 32768
#define DYN_BYTES (NSLOT * SLOTB)

typedef unsigned long long ull;
#define ONE2 0x3f8000003f800000ull

__device__ ull   g_part[Bn * NSC][Kn][NT];   // 2.6 MB chunk partials
__device__ float g_asum[Bn * NSC][Kn];
__device__ int   g_cnt[Bn];

__device__ __forceinline__ void fma2(ull& acc, ull a, ull f) {
    asm("fma.rn.f32x2 %0, %1, %2, %0;" : "+l"(acc) : "l"(a), "l"(f));
}
__device__ __forceinline__ uint32_t s2u(const void* p) {
    uint32_t a;
    asm("{ .reg .u64 t; cvta.to.shared.u64 t, %1; cvt.u32.u64 %0, t; }" : "=r"(a) : "l"(p));
    return a;
}
__device__ __forceinline__ void mbar_init(uint32_t mb, uint32_t cnt) {
    asm volatile("mbarrier.init.shared.b64 [%0], %1;" :: "r"(mb), "r"(cnt) : "memory");
}
__device__ __forceinline__ void mbar_expect_tx(uint32_t mb, uint32_t bytes) {
    asm volatile("mbarrier.arrive.expect_tx.shared.b64 _, [%0], %1;"
                 :: "r"(mb), "r"(bytes) : "memory");
}
__device__ __forceinline__ void mbar_arrive(uint32_t mb) {
    asm volatile("mbarrier.arrive.shared.b64 _, [%0];" :: "r"(mb) : "memory");
}
__device__ __forceinline__ void bulk_g2s(uint32_t dst, ull gsrc, uint32_t bytes, uint32_t mb) {
    asm volatile("cp.async.bulk.shared::cluster.global.mbarrier::complete_tx::bytes "
                 "[%0], [%1], %2, [%3];"
                 :: "r"(dst), "l"(gsrc), "r"(bytes), "r"(mb) : "memory");
}
__device__ __forceinline__ void mbar_wait(uint32_t mb, uint32_t parity) {
    uint32_t done;
    asm volatile("{\n\t.reg .pred p;\n\t"
                 "mbarrier.try_wait.parity.acquire.cta.shared::cta.b64 p, [%1], %2;\n\t"
                 "selp.b32 %0, 1, 0, p;\n\t}"
                 : "=r"(done) : "r"(mb), "r"(parity) : "memory");
    if (!done) {
        asm volatile("{\n\t.reg .pred P1;\n\t"
                     "W%=:\n\t"
                     "mbarrier.try_wait.parity.acquire.cta.shared::cta.b64 P1, [%0], %1, 0x989680;\n\t"
                     "@P1 bra.uni DW%=;\n\t"
                     "bra.uni W%=;\n\t"
                     "DW%=:\n\t}"
                     :: "r"(mb), "r"(parity) : "memory");
    }
}

__global__ __launch_bounds__(NT, 1)
void vlad_ring(const float* __restrict__ feat, const float* __restrict__ score,
               const float* __restrict__ cluster, float* __restrict__ out)
{
    extern __shared__ __align__(16) char ring[];     // 128 KB, 4 x 32 KB slots
    __shared__ __align__(16) ull Ash[CSL][Kn];       // duplicated {a,a} pairs, 10 KB
    __shared__ __align__(8)  ull mfull[NSLOT];
    __shared__ __align__(8)  ull mempty[NSLOT];
    __shared__ float wsum[4][Kn];
    __shared__ float asumT[Kn];
    __shared__ float invS[Kn];
    __shared__ float sqw[Kn][8];
    __shared__ int   isLast;

    const int tid = threadIdx.x;
    const int b  = blockIdx.x >> 3;
    const int sc = blockIdx.x & 7;
    const int chunk = b * NSC + sc;

    const uint32_t ringA = s2u(ring);
    const uint32_t mfA   = s2u(&mfull[0]);
    const uint32_t meA   = s2u(&mempty[0]);

    ull g0;
    {
        const float* p = feat + ((size_t)(b * Sn) + sc * CSL) * Dn;
        asm("cvta.to.global.u64 %0, %1;" : "=l"(g0) : "l"(p));
    }

    if (tid == 0) {
        #pragma unroll
        for (int s = 0; s < NSLOT; s++) { mbar_init(mfA + s * 8, 1); mbar_init(meA + s * 8, 8); }
    }
    __syncthreads();
    if (tid == 0) {   // prime PFD stages; they land while softmax runs
        #pragma unroll
        for (int p = 0; p < PFD; p++) {
            mbar_expect_tx(mfA + p * 8, SLOTB);
            bulk_g2s(ringA + p * SLOTB, g0 + (ull)p * SLOTB, SLOTB, mfA + p * 8);
        }
    }

    // ---- softmax: threads 0..127, one s-row each ----
    if (tid < CSL) {
        const float* sp = score + ((size_t)(b * Sn) + sc * CSL + tid) * KCn;
        float4 v0 = *(const float4*)sp;
        float4 v1 = *(const float4*)(sp + 4);
        float4 v2 = *(const float4*)(sp + 8);
        float v[KCn] = {v0.x, v0.y, v0.z, v0.w, v1.x, v1.y, v1.z, v1.w,
                        v2.x, v2.y, v2.z, v2.w};
        float sum = 0.f;
        #pragma unroll
        for (int k = 0; k < KCn; k++) { v[k] = __expf(v[k]); sum += v[k]; }
        float inv = 1.f / sum;
        #pragma unroll
        for (int k = 0; k < Kn; k++) {
            float a = v[k] * inv;
            unsigned int u = __float_as_uint(a);
            Ash[tid][k] = ((ull)u << 32) | (ull)u;
            float s = a;
            #pragma unroll
            for (int o = 16; o > 0; o >>= 1) s += __shfl_xor_sync(0xffffffffu, s, o);
            if ((tid & 31) == 0) wsum[tid >> 5][k] = s;
        }
    }
    __syncthreads();   // Ash complete before any warp consumes stage 0
    if (tid < Kn)
        g_asum[chunk][tid] = wsum[0][tid] + wsum[1][tid] + wsum[2][tid] + wsum[3][tid];

    // ---- main loop: free-running warps over 8 stages; thread owns d-pair tid ----
    ull acc[Kn];
    #pragma unroll
    for (int k = 0; k < Kn; k++) acc[k] = 0ull;

    for (int st = 0; st < NSTG; st++) {
        const int slot = st & (NSLOT - 1);
        mbar_wait(mfA + slot * 8, (uint32_t)((st >> 2) & 1));

        // producer: prefetch stage st+PFD (slot freed once all warps passed st-1)
        if (tid == 0) {
            const int ns = st + PFD;
            if (ns < NSTG) {
                const int nslot = ns & (NSLOT - 1);
                if (ns >= NSLOT) mbar_wait(meA + nslot * 8, 0);   // 8 stages: reuse round 1
                mbar_expect_tx(mfA + nslot * 8, SLOTB);
                bulk_g2s(ringA + nslot * SLOTB, g0 + (ull)ns * SLOTB, SLOTB, mfA + nslot * 8);
            }
        }

        const char* sb = ring + slot * SLOTB;
        #pragma unroll
        for (int r = 0; r < SR; r++) {
            ull f = *(const ull*)(sb + r * 2048 + tid * 8);
            const ulonglong2* ar = (const ulonglong2*)Ash[st * SR + r];
            ulonglong2 a01 = ar[0], a23 = ar[1], a45 = ar[2], a67 = ar[3], a89 = ar[4];
            fma2(acc[0], a01.x, f); fma2(acc[1], a01.y, f);
            fma2(acc[2], a23.x, f); fma2(acc[3], a23.y, f);
            fma2(acc[4], a45.x, f); fma2(acc[5], a45.y, f);
            fma2(acc[6], a67.x, f); fma2(acc[7], a67.y, f);
            fma2(acc[8], a89.x, f); fma2(acc[9], a89.y, f);
        }
        __syncwarp();
        if ((tid & 31) == 0) mbar_arrive(meA + slot * 8);   // this warp done with slot
    }

    // ---- write chunk partial (thread owns its slot) ----
    #pragma unroll
    for (int k = 0; k < Kn; k++) g_part[chunk][k][tid] = acc[k];

    // ---- last CTA of this batch merges the 8 chunk partials (R9 tail) ----
    __threadfence();
    __syncthreads();
    if (tid == 0) isLast = (atomicAdd(&g_cnt[b], 1) == NSC - 1);
    __syncthreads();
    if (!isLast) return;
    __threadfence();

    if (tid < Kn) {
        float s = 0.f;
        #pragma unroll
        for (int c = 0; c < NSC; c++) s += g_asum[b * NSC + c][tid];
        asumT[tid] = s;
    }
    __syncthreads();

    float2 r[Kn];
    #pragma unroll
    for (int k = 0; k < Kn; k++) {
        ull a = g_part[b * NSC][k][tid];
        #pragma unroll
        for (int c = 1; c < NSC; c++) fma2(a, g_part[b * NSC + c][k][tid], ONE2);
        const float as = asumT[k];
        float2 cl = *(const float2*)(cluster + k * Dn + tid * 2);
        r[k].x = __uint_as_float((unsigned int)a)         - as * cl.x;
        r[k].y = __uint_as_float((unsigned int)(a >> 32)) - as * cl.y;
        float s = r[k].x * r[k].x + r[k].y * r[k].y;
        #pragma unroll
        for (int o = 16; o > 0; o >>= 1) s += __shfl_xor_sync(0xffffffffu, s, o);
        if ((tid & 31) == 0) sqw[k][tid >> 5] = s;
    }
    __syncthreads();
    if (tid < Kn) {
        float s = 0.f;
        #pragma unroll
        for (int w = 0; w < 8; w++) s += sqw[tid][w];
        invS[tid] = rsqrtf(fmaxf(s, 1e-12f));
    }
    __syncthreads();

    ull* ob = (ull*)out + (size_t)b * (Kn * Dn / 2);
    #pragma unroll
    for (int k = 0; k < Kn; k++) {
        const float iv = invS[k];
        unsigned int ux = __float_as_uint(r[k].x * iv);
        unsigned int uy = __float_as_uint(r[k].y * iv);
        ob[k * (Dn / 2) + tid] = ((ull)uy << 32) | (ull)ux;
    }
    if (tid == 0) g_cnt[b] = 0;   // reset for next graph replay
}

extern "C" void kernel_launch(void* const* d_in, const int* in_sizes, int n_in,
                              void* d_out, int out_size) {
    const float* feat    = (const float*)d_in[0];  // (16,16,64,512) f32
    const float* score   = (const float*)d_in[1];  // (16,16,64,12)  f32
    const float* cluster = (const float*)d_in[2];  // (12,512)       f32
    float* out = (float*)d_out;                    // (16,5120)      f32

    static int attr_set = 0;
    if (!attr_set) {
        cudaFuncSetAttribute(vlad_ring, cudaFuncAttributeMaxDynamicSharedMemorySize,
                             DYN_BYTES);
        attr_set = 1;
    }
    vlad_ring<<<Bn * NSC, NT, DYN_BYTES>>>(feat, score, cluster, out);
}